// round 12
// baseline (speedup 1.0000x reference)
#include <cuda_runtime.h>
#include <cuda_fp16.h>
#include <math.h>
#include <stdint.h>

// Problem constants
#define NEMBD 1024
#define NHEAD 16
#define HDIM  64
#define TSEQ  2048
#define BATCH 4
#define BH    (BATCH * NHEAD)
#define QSCALE 0.18033688011112042f   // 0.125 * log2(e)

// ---------------------------------------------------------------------------
// Scratch (device globals)
// ---------------------------------------------------------------------------
__device__ __half g_a_hi[(size_t)BATCH * TSEQ * NEMBD];
__device__ __half g_a_lo[(size_t)BATCH * TSEQ * NEMBD];
__device__ __half g_wq[(size_t)3 * NEMBD * NEMBD];
__device__ __half g_wp[(size_t)NEMBD * NEMBD];
__device__ __half g_q_hi[(size_t)BH * TSEQ * HDIM];
__device__ __half g_q_lo[(size_t)BH * TSEQ * HDIM];
__device__ __half g_k[(size_t)BH * TSEQ * HDIM];
__device__ __half g_v[(size_t)BH * TSEQ * HDIM];

// ---------------------------------------------------------------------------
// PTX helpers
// ---------------------------------------------------------------------------
__device__ __forceinline__ uint32_t smem_u32(const void* p) {
    uint32_t a;
    asm("{ .reg .u64 t; cvta.to.shared.u64 t, %1; cvt.u32.u64 %0, t; }" : "=r"(a) : "l"(p));
    return a;
}
#define CP_ASYNC16(sm, gm) \
    asm volatile("cp.async.cg.shared.global [%0], [%1], 16;" :: "r"(sm), "l"(gm))
#define CP_COMMIT() asm volatile("cp.async.commit_group;" ::: "memory")
#define CP_WAIT(n)  asm volatile("cp.async.wait_group %0;" :: "n"(n) : "memory")

#define LDSM_X4(r0, r1, r2, r3, a) \
    asm volatile("ldmatrix.sync.aligned.m8n8.x4.shared.b16 {%0,%1,%2,%3}, [%4];" \
        : "=r"(r0), "=r"(r1), "=r"(r2), "=r"(r3) : "r"(a))
#define LDSM_X4_T(r0, r1, r2, r3, a) \
    asm volatile("ldmatrix.sync.aligned.m8n8.x4.trans.shared.b16 {%0,%1,%2,%3}, [%4];" \
        : "=r"(r0), "=r"(r1), "=r"(r2), "=r"(r3) : "r"(a))

__device__ __forceinline__ void mma_bb(float* c, const uint32_t* a, uint32_t b0, uint32_t b1) {
    asm volatile(
        "mma.sync.aligned.m16n8k16.row.col.f32.f16.f16.f32 "
        "{%0,%1,%2,%3}, {%4,%5,%6,%7}, {%8,%9}, {%0,%1,%2,%3};"
        : "+f"(c[0]), "+f"(c[1]), "+f"(c[2]), "+f"(c[3])
        : "r"(a[0]), "r"(a[1]), "r"(a[2]), "r"(a[3]), "r"(b0), "r"(b1));
}
__device__ __forceinline__ uint32_t pack_h2(float a, float b) {
    __half2 h = __floats2half2_rn(a, b);
    return *(uint32_t*)&h;
}
__device__ __forceinline__ float exp2p(float t) {
    t = fmaxf(t, -126.0f);
    float fi = rintf(t);
    float f = t - fi;
    float p = 0.0013333558f;
    p = fmaf(p, f, 0.0096181291f);
    p = fmaf(p, f, 0.0555041087f);
    p = fmaf(p, f, 0.2402265070f);
    p = fmaf(p, f, 0.6931471806f);
    p = fmaf(p, f, 1.0f);
    int ii = (int)fi;
    return p * __int_as_float((uint32_t)(ii + 127) << 23);
}

// ---------------------------------------------------------------------------
// Conversion kernels
// ---------------------------------------------------------------------------
__global__ __launch_bounds__(256)
void split_kernel(const float* __restrict__ in, __half* __restrict__ hi,
                  __half* __restrict__ lo, int n4)
{
    int idx = blockIdx.x * blockDim.x + threadIdx.x;
    if (idx >= n4) return;
    float4 v = ((const float4*)in)[idx];
    __half h[4], l[4];
    float f[4] = {v.x, v.y, v.z, v.w};
#pragma unroll
    for (int i = 0; i < 4; ++i) {
        h[i] = __float2half_rn(f[i]);
        l[i] = __float2half_rn(f[i] - __half2float(h[i]));
    }
    ((uint2*)hi)[idx] = *(const uint2*)h;
    ((uint2*)lo)[idx] = *(const uint2*)l;
}

__global__ __launch_bounds__(256)
void tsplit_kernel(const float* __restrict__ w, __half* __restrict__ wt, int K, int N)
{
    __shared__ float t[32][33];
    const int n0 = blockIdx.x * 32;
    const int k0 = blockIdx.y * 32;
#pragma unroll
    for (int i = 0; i < 4; ++i) {
        int kk = threadIdx.y + i * 8;
        t[kk][threadIdx.x] = w[(size_t)(k0 + kk) * N + n0 + threadIdx.x];
    }
    __syncthreads();
#pragma unroll
    for (int i = 0; i < 4; ++i) {
        int nn = threadIdx.y + i * 8;
        int kk = threadIdx.x;
        wt[(size_t)(n0 + nn) * K + k0 + kk] = __float2half_rn(t[kk][nn]);
    }
}

// ---------------------------------------------------------------------------
// Shared tile constants
// ---------------------------------------------------------------------------
#define BK 32
#define ASTR 40
#define A_TILE_B (128 * ASTR * 2)
#define B64_TILE_B (64 * ASTR * 2)
#define B128_TILE_B (128 * ASTR * 2)

// ---------------------------------------------------------------------------
// 2-product GEMM, BN=64 (q path). Hi/lo MMA passes separated (RAW distance 8).
// ---------------------------------------------------------------------------
#define GBUF2 (2 * A_TILE_B + B64_TILE_B)
#define SMEM2 (3 * GBUF2)

__global__ __launch_bounds__(256, 2)
void gemm_q_kernel(const __half* __restrict__ Ahi,
                   const __half* __restrict__ Alo,
                   const __half* __restrict__ B,
                   uint32_t* __restrict__ qhi, uint32_t* __restrict__ qlo,
                   int K)
{
    extern __shared__ char smem[];
    const uint32_t sbase = smem_u32(smem);
    const int tid = threadIdx.x;
    const int wid = tid >> 5;
    const int lane = tid & 31;
    const int grp = lane >> 2;
    const int tig = lane & 3;
    const int warp_m = wid & 3;
    const int warp_n = wid >> 2;
    const int rowBase = blockIdx.y * 128;
    const int colBase = blockIdx.x * 64;

    const int a_row = lane & 15;
    const int a_kh  = (lane >> 4) * 8;
    uint32_t aoff[2];
#pragma unroll
    for (int mt = 0; mt < 2; ++mt)
        aoff[mt] = (uint32_t)(((warp_m * 32 + mt * 16 + a_row) * ASTR + a_kh) * 2);
    const int b_n  = (lane & 7) + ((lane >> 4) & 1) * 8;
    const int b_kh = ((lane >> 3) & 1) * 8;
    uint32_t boff[2];
#pragma unroll
    for (int np = 0; np < 2; ++np)
        boff[np] = (uint32_t)(((warp_n * 32 + np * 16 + b_n) * ASTR + b_kh) * 2);

    float acc[2][4][4];
#pragma unroll
    for (int i = 0; i < 2; ++i)
#pragma unroll
        for (int j = 0; j < 4; ++j)
#pragma unroll
            for (int k = 0; k < 4; ++k) acc[i][j][k] = 0.0f;

    const int nstages = K / BK;

#define LOAD_STAGE_Q(s) do {                                                    \
        const int _k0 = (s) * BK;                                               \
        const uint32_t _buf = sbase + ((s) % 3) * GBUF2;                        \
        _Pragma("unroll")                                                       \
        for (int _i = 0; _i < 2; ++_i) {                                        \
            int _idx = tid + _i * 256;                                          \
            int _r = _idx >> 2, _c = _idx & 3;                                  \
            CP_ASYNC16(_buf + _r * (ASTR * 2) + _c * 16,                        \
                       Ahi + (size_t)(rowBase + _r) * K + _k0 + _c * 8);        \
            CP_ASYNC16(_buf + A_TILE_B + _r * (ASTR * 2) + _c * 16,             \
                       Alo + (size_t)(rowBase + _r) * K + _k0 + _c * 8);        \
        }                                                                       \
        {                                                                       \
            int _r = tid >> 2, _c = tid & 3;                                    \
            CP_ASYNC16(_buf + 2 * A_TILE_B + _r * (ASTR * 2) + _c * 16,         \
                       B + (size_t)(colBase + _r) * K + _k0 + _c * 8);          \
        }                                                                       \
        CP_COMMIT();                                                            \
    } while (0)

    LOAD_STAGE_Q(0);
    LOAD_STAGE_Q(1);

    for (int s = 0; s < nstages; ++s) {
        if (s + 2 < nstages) { LOAD_STAGE_Q(s + 2); CP_WAIT(2); }
        else if (s + 1 < nstages) { CP_WAIT(1); }
        else { CP_WAIT(0); }
        __syncthreads();

        const uint32_t buf = sbase + (s % 3) * GBUF2;
        const uint32_t smAh = buf;
        const uint32_t smAl = buf + A_TILE_B;
        const uint32_t smB  = buf + 2 * A_TILE_B;

#pragma unroll
        for (int kkk = 0; kkk < BK; kkk += 16) {
            uint32_t ah[2][4], al[2][4], bf[2][4];
#pragma unroll
            for (int mt = 0; mt < 2; ++mt) {
                LDSM_X4(ah[mt][0], ah[mt][1], ah[mt][2], ah[mt][3], smAh + aoff[mt] + kkk * 2);
                LDSM_X4(al[mt][0], al[mt][1], al[mt][2], al[mt][3], smAl + aoff[mt] + kkk * 2);
            }
#pragma unroll
            for (int np = 0; np < 2; ++np)
                LDSM_X4(bf[np][0], bf[np][1], bf[np][2], bf[np][3], smB + boff[np] + kkk * 2);
            // Pass 1: all hi products (8 independent accumulators)
#pragma unroll
            for (int mt = 0; mt < 2; ++mt)
#pragma unroll
                for (int nt = 0; nt < 4; ++nt)
                    mma_bb(acc[mt][nt], ah[mt],
                           bf[nt >> 1][(nt & 1) * 2], bf[nt >> 1][(nt & 1) * 2 + 1]);
            // Pass 2: all lo products (RAW distance 8)
#pragma unroll
            for (int mt = 0; mt < 2; ++mt)
#pragma unroll
                for (int nt = 0; nt < 4; ++nt)
                    mma_bb(acc[mt][nt], al[mt],
                           bf[nt >> 1][(nt & 1) * 2], bf[nt >> 1][(nt & 1) * 2 + 1]);
        }
        __syncthreads();
    }

    const int h = colBase >> 6;
#pragma unroll
    for (int mt = 0; mt < 2; ++mt) {
        const int r0 = rowBase + warp_m * 32 + mt * 16 + grp;
#pragma unroll
        for (int hf = 0; hf < 2; ++hf) {
            const int r = r0 + hf * 8;
            const int b = r >> 11;
            const int t = r & (TSEQ - 1);
            const size_t bhT = (size_t)(b * NHEAD + h) * TSEQ + t;
#pragma unroll
            for (int nt = 0; nt < 4; ++nt) {
                float v0 = acc[mt][nt][hf * 2], v1 = acc[mt][nt][hf * 2 + 1];
                const int dw = warp_n * 16 + nt * 4 + tig;
                float q0 = v0 * QSCALE, q1 = v1 * QSCALE;
                uint32_t hp = pack_h2(q0, q1);
                float2 fr = __half22float2(*(__half2*)&hp);
                qhi[bhT * 32 + dw] = hp;
                qlo[bhT * 32 + dw] = pack_h2(q0 - fr.x, q1 - fr.y);
            }
        }
    }
#undef LOAD_STAGE_Q
}

// ---------------------------------------------------------------------------
// 1-product GEMM, BN=128. MODE 0: fp32 C.  MODE 2: k/v epilogue.
// ---------------------------------------------------------------------------
#define GBUFW (A_TILE_B + B128_TILE_B)
#define SMEMW (3 * GBUFW)

template<int MODE>
__global__ __launch_bounds__(256, 2)
void gemm_wide_kernel(const __half* __restrict__ Ahi,
                      const __half* __restrict__ B,
                      float* __restrict__ C,
                      uint32_t* __restrict__ kk, uint32_t* __restrict__ vv,
                      int N, int K, int colOff)
{
    extern __shared__ char smem[];
    const uint32_t sbase = smem_u32(smem);
    const int tid = threadIdx.x;
    const int wid = tid >> 5;
    const int lane = tid & 31;
    const int grp = lane >> 2;
    const int tig = lane & 3;
    const int warp_m = wid & 3;
    const int warp_n = wid >> 2;
    const int rowBase = blockIdx.y * 128;
    const int colBase = blockIdx.x * 128;

    const int a_row = lane & 15;
    const int a_kh  = (lane >> 4) * 8;
    uint32_t aoff[2];
#pragma unroll
    for (int mt = 0; mt < 2; ++mt)
        aoff[mt] = (uint32_t)(((warp_m * 32 + mt * 16 + a_row) * ASTR + a_kh) * 2);
    const int b_n  = (lane & 7) + ((lane >> 4) & 1) * 8;
    const int b_kh = ((lane >> 3) & 1) * 8;
    uint32_t boff[4];
#pragma unroll
    for (int np = 0; np < 4; ++np)
        boff[np] = (uint32_t)(((warp_n * 64 + np * 16 + b_n) * ASTR + b_kh) * 2);

    float acc[2][8][4];
#pragma unroll
    for (int i = 0; i < 2; ++i)
#pragma unroll
        for (int j = 0; j < 8; ++j)
#pragma unroll
            for (int k = 0; k < 4; ++k) acc[i][j][k] = 0.0f;

    const int nstages = K / BK;

#define LOAD_STAGE_W(s) do {                                                    \
        const int _k0 = (s) * BK;                                               \
        const uint32_t _buf = sbase + ((s) % 3) * GBUFW;                        \
        _Pragma("unroll")                                                       \
        for (int _i = 0; _i < 2; ++_i) {                                        \
            int _idx = tid + _i * 256;                                          \
            int _r = _idx >> 2, _c = _idx & 3;                                  \
            CP_ASYNC16(_buf + _r * (ASTR * 2) + _c * 16,                        \
                       Ahi + (size_t)(rowBase + _r) * K + _k0 + _c * 8);        \
            CP_ASYNC16(_buf + A_TILE_B + _r * (ASTR * 2) + _c * 16,             \
                       B + (size_t)(colBase + _r) * K + _k0 + _c * 8);          \
        }                                                                       \
        CP_COMMIT();                                                            \
    } while (0)

    LOAD_STAGE_W(0);
    LOAD_STAGE_W(1);

    for (int s = 0; s < nstages; ++s) {
        if (s + 2 < nstages) { LOAD_STAGE_W(s + 2); CP_WAIT(2); }
        else if (s + 1 < nstages) { CP_WAIT(1); }
        else { CP_WAIT(0); }
        __syncthreads();

        const uint32_t buf = sbase + (s % 3) * GBUFW;
        const uint32_t smA = buf;
        const uint32_t smB = buf + A_TILE_B;

#pragma unroll
        for (int kkk = 0; kkk < BK; kkk += 16) {
            uint32_t ah[2][4], bf[4][4];
#pragma unroll
            for (int mt = 0; mt < 2; ++mt)
                LDSM_X4(ah[mt][0], ah[mt][1], ah[mt][2], ah[mt][3], smA + aoff[mt] + kkk * 2);
#pragma unroll
            for (int np = 0; np < 4; ++np)
                LDSM_X4(bf[np][0], bf[np][1], bf[np][2], bf[np][3], smB + boff[np] + kkk * 2);
#pragma unroll
            for (int mt = 0; mt < 2; ++mt)
#pragma unroll
                for (int nt = 0; nt < 8; ++nt)
                    mma_bb(acc[mt][nt], ah[mt],
                           bf[nt >> 1][(nt & 1) * 2], bf[nt >> 1][(nt & 1) * 2 + 1]);
        }
        __syncthreads();
    }

    if (MODE == 0) {
#pragma unroll
        for (int mt = 0; mt < 2; ++mt) {
            int r = rowBase + warp_m * 32 + mt * 16 + grp;
#pragma unroll
            for (int nt = 0; nt < 8; ++nt) {
                int c = colBase + warp_n * 64 + nt * 8 + tig * 2;
                *(float2*)(C + (size_t)r * N + c) = make_float2(acc[mt][nt][0], acc[mt][nt][1]);
                *(float2*)(C + (size_t)(r + 8) * N + c) = make_float2(acc[mt][nt][2], acc[mt][nt][3]);
            }
        }
    } else {
#pragma unroll
        for (int mt = 0; mt < 2; ++mt) {
            const int r0 = rowBase + warp_m * 32 + mt * 16 + grp;
#pragma unroll
            for (int hf = 0; hf < 2; ++hf) {
                const int r = r0 + hf * 8;
                const int b = r >> 11;
                const int t = r & (TSEQ - 1);
#pragma unroll
                for (int nt = 0; nt < 8; ++nt) {
                    const int col = colOff + colBase + warp_n * 64 + nt * 8;
                    const int sec = col >> 10;
                    const int h = (col & 1023) >> 6;
                    const int dw = ((col & 63) >> 1) + tig;
                    const size_t bhT = (size_t)(b * NHEAD + h) * TSEQ + t;
                    uint32_t hp = pack_h2(acc[mt][nt][hf * 2], acc[mt][nt][hf * 2 + 1]);
                    if (sec == 1) kk[bhT * 32 + dw] = hp;
                    else          vv[bhT * 32 + dw] = hp;
                }
            }
        }
    }
#undef LOAD_STAGE_W
}

// ---------------------------------------------------------------------------
// HMMA flash attention: S 2-product (hi/lo passes separated), P@V 1-product
// via ldmatrix.trans. V natural [bh][t][d].
// ---------------------------------------------------------------------------
#define AQ  128
#define AKV 64
#define KSW 36
#define VSW 36
#define QHI_W 0
#define QLO_W 4608
#define STG0_W 9216
#define STG_SZ_W 4608
#define KOFF_W 0
#define VOFF_W 2304
#define ATTN_SMEM_B ((STG0_W + 2 * STG_SZ_W) * 4)

__global__ __launch_bounds__(256, 2)
void attn_hmma_kernel(const __half* __restrict__ Qh, const __half* __restrict__ Ql,
                      const __half* __restrict__ Kt, const __half* __restrict__ Vh,
                      uint32_t* __restrict__ yhi)
{
    extern __shared__ uint32_t smw[];
    const uint32_t sbase = smem_u32(smw);
    const int tid = threadIdx.x;
    const int warp = tid >> 5;
    const int lane = tid & 31;
    const int grp = lane >> 2;
    const int tig = lane & 3;
    const int qb = (int)(gridDim.x - 1 - blockIdx.x);
    const int bh = blockIdx.y;
    const int q0 = qb * AQ;
    const size_t bhT = (size_t)bh * TSEQ;

    const int a_row = lane & 15;
    const int a_kh  = (lane >> 4) * 8;
    const int b_n   = (lane & 7) + ((lane >> 4) & 1) * 8;
    const int b_kh  = ((lane >> 3) & 1) * 8;

#pragma unroll
    for (int i = 0; i < 4; ++i) {
        int idx = tid + i * 256;
        int r = idx >> 3, c = idx & 7;
        CP_ASYNC16(sbase + (QHI_W + r * KSW) * 4 + c * 16, Qh + (bhT + q0 + r) * HDIM + c * 8);
        CP_ASYNC16(sbase + (QLO_W + r * KSW) * 4 + c * 16, Ql + (bhT + q0 + r) * HDIM + c * 8);
    }
    CP_COMMIT();

#define LOAD_KV(kb_, st_) do {                                                          \
        const int _kv0 = (kb_) * AKV;                                                  \
        const uint32_t _sb = sbase + (STG0_W + (st_) * STG_SZ_W) * 4;                   \
        _Pragma("unroll")                                                               \
        for (int _i = 0; _i < 2; ++_i) {                                                \
            int _idx = tid + _i * 256;                                                  \
            int _r = _idx >> 3, _c = _idx & 7;                                          \
            CP_ASYNC16(_sb + (KOFF_W + _r * KSW) * 4 + _c * 16,                         \
                       Kt + (bhT + _kv0 + _r) * HDIM + _c * 8);                         \
        }                                                                               \
        _Pragma("unroll")                                                               \
        for (int _i = 0; _i < 2; ++_i) {                                                \
            int _idx = tid + _i * 256;                                                  \
            int _r = _idx >> 3, _c = _idx & 7;                                          \
            CP_ASYNC16(_sb + (VOFF_W + _r * VSW) * 4 + _c * 16,                         \
                       Vh + (bhT + _kv0 + _r) * HDIM + _c * 8);                         \
        }                                                                               \
        CP_COMMIT();                                                                    \
    } while (0)

    LOAD_KV(0, 0);
    CP_WAIT(0);
    __syncthreads();

    uint32_t qfh[4][4], qfl[4][4];
    {
        const uint32_t qrow = (uint32_t)((warp * 16 + a_row) * KSW);
#pragma unroll
        for (int ks = 0; ks < 4; ++ks) {
            uint32_t ao = sbase + (QHI_W + qrow) * 4 + (ks * 16 + a_kh) * 2;
            LDSM_X4(qfh[ks][0], qfh[ks][1], qfh[ks][2], qfh[ks][3], ao);
            uint32_t al_ = ao + (QLO_W - QHI_W) * 4;
            LDSM_X4(qfl[ks][0], qfl[ks][1], qfl[ks][2], qfl[ks][3], al_);
        }
    }

    float o[8][4];
#pragma unroll
    for (int i = 0; i < 8; ++i)
#pragma unroll
        for (int j = 0; j < 4; ++j) o[i][j] = 0.0f;
    float m0 = -1e30f, m1 = -1e30f, l0 = 0.0f, l1 = 0.0f;

    const int nkb = 2 * (qb + 1);
    for (int kb = 0; kb < nkb; ++kb) {
        if (kb) { CP_WAIT(0); __syncthreads(); }
        if (kb + 1 < nkb) LOAD_KV(kb + 1, (kb + 1) & 1);

        const uint32_t stw = STG0_W + (kb & 1) * STG_SZ_W;
        const uint32_t kW = stw + KOFF_W;
        const uint32_t vW = stw + VOFF_W;

        float s[8][4];
#pragma unroll
        for (int i = 0; i < 8; ++i)
            s[i][0] = s[i][1] = s[i][2] = s[i][3] = 0.0f;
        // S = Q @ K^T: per ks, load all K frags, then hi pass (8 indep) + lo pass.
#pragma unroll
        for (int ks = 0; ks < 4; ++ks) {
            uint32_t bf[4][4];
#pragma unroll
            for (int np = 0; np < 4; ++np) {
                const uint32_t krow = sbase + (kW + (np * 16 + b_n) * KSW) * 4;
                LDSM_X4(bf[np][0], bf[np][1], bf[np][2], bf[np][3],
                        krow + (ks * 16 + b_kh) * 2);
            }
#pragma unroll
            for (int np = 0; np < 4; ++np) {
                mma_bb(s[np * 2],     qfh[ks], bf[np][0], bf[np][1]);
                mma_bb(s[np * 2 + 1], qfh[ks], bf[np][2], bf[np][3]);
            }
#pragma unroll
            for (int np = 0; np < 4; ++np) {
                mma_bb(s[np * 2],     qfl[ks], bf[np][0], bf[np][1]);
                mma_bb(s[np * 2 + 1], qfl[ks], bf[np][2], bf[np][3]);
            }
        }

        if (kb >= nkb - 2) {
            const int kv0 = kb * AKV;
            const int r0g = q0 + warp * 16 + grp;
            const int r1g = r0g + 8;
#pragma unroll
            for (int nt = 0; nt < 8; ++nt) {
                int c0 = kv0 + nt * 8 + tig * 2;
                if (c0 > r0g)     s[nt][0] = -1e30f;
                if (c0 + 1 > r0g) s[nt][1] = -1e30f;
                if (c0 > r1g)     s[nt][2] = -1e30f;
                if (c0 + 1 > r1g) s[nt][3] = -1e30f;
            }
        }

        float mx0 = -1e30f, mx1 = -1e30f;
#pragma unroll
        for (int nt = 0; nt < 8; ++nt) {
            mx0 = fmaxf(mx0, fmaxf(s[nt][0], s[nt][1]));
            mx1 = fmaxf(mx1, fmaxf(s[nt][2], s[nt][3]));
        }
        mx0 = fmaxf(mx0, __shfl_xor_sync(0xffffffffu, mx0, 1));
        mx0 = fmaxf(mx0, __shfl_xor_sync(0xffffffffu, mx0, 2));
        mx1 = fmaxf(mx1, __shfl_xor_sync(0xffffffffu, mx1, 1));
        mx1 = fmaxf(mx1, __shfl_xor_sync(0xffffffffu, mx1, 2));
        float mn0 = fmaxf(m0, mx0), mn1 = fmaxf(m1, mx1);
        float a0 = exp2p(m0 - mn0), a1 = exp2p(m1 - mn1);
        m0 = mn0; m1 = mn1;
        l0 *= a0; l1 *= a1;
#pragma unroll
        for (int nt = 0; nt < 8; ++nt) {
            o[nt][0] *= a0; o[nt][1] *= a0;
            o[nt][2] *= a1; o[nt][3] *= a1;
        }
        float sum0 = 0.0f, sum1 = 0.0f;
#pragma unroll
        for (int nt = 0; nt < 8; ++nt) {
            float p0 = exp2p(s[nt][0] - m0);
            float p1 = exp2p(s[nt][1] - m0);
            float p2 = exp2p(s[nt][2] - m1);
            float p3 = exp2p(s[nt][3] - m1);
            sum0 += p0 + p1; sum1 += p2 + p3;
            s[nt][0] = p0; s[nt][1] = p1; s[nt][2] = p2; s[nt][3] = p3;
        }
        l0 += sum0; l1 += sum1;

#pragma unroll
        for (int j = 0; j < 4; ++j) {
            uint32_t ah4[4];
#pragma unroll
            for (int u = 0; u < 2; ++u) {
                const float* pv = s[2 * j + u];
                ah4[u * 2 + 0] = pack_h2(pv[0], pv[1]);
                ah4[u * 2 + 1] = pack_h2(pv[2], pv[3]);
            }
#pragma unroll
            for (int np = 0; np < 4; ++np) {
                uint32_t v0, v1, v2, v3;
                uint32_t vaddr = sbase + (vW + (j * 16 + a_row) * VSW) * 4
                               + (np * 16 + a_kh) * 2;
                LDSM_X4_T(v0, v1, v2, v3, vaddr);
                mma_bb(o[np * 2],     ah4, v0, v1);
                mma_bb(o[np * 2 + 1], ah4, v2, v3);
            }
        }
    }

    l0 += __shfl_xor_sync(0xffffffffu, l0, 1);
    l0 += __shfl_xor_sync(0xffffffffu, l0, 2);
    l1 += __shfl_xor_sync(0xffffffffu, l1, 1);
    l1 += __shfl_xor_sync(0xffffffffu, l1, 2);
    const float inv0 = 1.0f / l0, inv1 = 1.0f / l1;

    const int b = bh >> 4, h = bh & 15;
    const int rowg = q0 + warp * 16 + grp;
    const size_t base0 = ((size_t)(b * TSEQ) + rowg) * (NEMBD / 2) + h * (HDIM / 2);
    const size_t base1 = base0 + 8 * (NEMBD / 2);
#pragma unroll
    for (int nt = 0; nt < 8; ++nt) {
        int cw = nt * 4 + tig;
        yhi[base0 + cw] = pack_h2(o[nt][0] * inv0, o[nt][1] * inv0);
        yhi[base1 + cw] = pack_h2(o[nt][2] * inv1, o[nt][3] * inv1);
    }
#undef LOAD_KV
}

// ---------------------------------------------------------------------------
// Launch
// ---------------------------------------------------------------------------
extern "C" void kernel_launch(void* const* d_in, const int* in_sizes, int n_in,
                              void* d_out, int out_size)
{
    const float* x      = (const float*)d_in[0];
    const float* w_attn = (const float*)d_in[1];
    const float* w_proj = (const float*)d_in[2];
    float* out = (float*)d_out;

    __half *ahi, *alo, *wq, *wp, *qhi, *qlo, *kk, *vv;
    cudaGetSymbolAddress((void**)&ahi, g_a_hi);
    cudaGetSymbolAddress((void**)&alo, g_a_lo);
    cudaGetSymbolAddress((void**)&wq, g_wq);
    cudaGetSymbolAddress((void**)&wp, g_wp);
    cudaGetSymbolAddress((void**)&qhi, g_q_hi);
    cudaGetSymbolAddress((void**)&qlo, g_q_lo);
    cudaGetSymbolAddress((void**)&kk, g_k);
    cudaGetSymbolAddress((void**)&vv, g_v);

    cudaFuncSetAttribute(gemm_q_kernel,
                         cudaFuncAttributeMaxDynamicSharedMemorySize, SMEM2);
    cudaFuncSetAttribute(gemm_wide_kernel<0>,
                         cudaFuncAttributeMaxDynamicSharedMemorySize, SMEMW);
    cudaFuncSetAttribute(gemm_wide_kernel<2>,
                         cudaFuncAttributeMaxDynamicSharedMemorySize, SMEMW);
    cudaFuncSetAttribute(attn_hmma_kernel,
                         cudaFuncAttributeMaxDynamicSharedMemorySize, ATTN_SMEM_B);

    const int M = BATCH * TSEQ;
    const int K = NEMBD;

    {
        int n4 = (M * K) / 4;
        split_kernel<<<(n4 + 255) / 256, 256>>>(x, ahi, alo, n4);
    }
    {
        dim3 g1((3 * NEMBD) / 32, K / 32);
        tsplit_kernel<<<g1, dim3(32, 8)>>>(w_attn, wq, K, 3 * NEMBD);
        dim3 g2(NEMBD / 32, K / 32);
        tsplit_kernel<<<g2, dim3(32, 8)>>>(w_proj, wp, K, NEMBD);
    }
    {
        dim3 grid(NEMBD / 64, M / 128);
        gemm_q_kernel<<<grid, 256, SMEM2>>>(ahi, alo, wq,
                                            (uint32_t*)qhi, (uint32_t*)qlo, K);
    }
    {
        dim3 grid((2 * NEMBD) / 128, M / 128);
        gemm_wide_kernel<2><<<grid, 256, SMEMW>>>(
            ahi, wq + (size_t)NEMBD * K, nullptr,
            (uint32_t*)kk, (uint32_t*)vv, 0, K, NEMBD);
    }
    {
        dim3 grid(TSEQ / AQ, BH);
        attn_hmma_kernel<<<grid, 256, ATTN_SMEM_B>>>(qhi, qlo, kk, vv, (uint32_t*)ahi);
    }
    {
        dim3 grid(NEMBD / 128, M / 128);
        gemm_wide_kernel<0><<<grid, 256, SMEMW>>>(
            ahi, wp, out, nullptr, nullptr, NEMBD, K, 0);
    }
}

// round 13
// speedup vs baseline: 1.1298x; 1.1298x over previous
#include <cuda_runtime.h>
#include <cuda_fp16.h>
#include <math.h>
#include <stdint.h>

// Problem constants
#define NEMBD 1024
#define NHEAD 16
#define HDIM  64
#define TSEQ  2048
#define BATCH 4
#define BH    (BATCH * NHEAD)
#define QSCALE 0.18033688011112042f   // 0.125 * log2(e)

// ---------------------------------------------------------------------------
// Scratch (device globals)
// ---------------------------------------------------------------------------
__device__ __half g_a[(size_t)BATCH * TSEQ * NEMBD];      // x fp16, then y fp16
__device__ __half g_wq[(size_t)3 * NEMBD * NEMBD];        // w_attn^T [3072][1024] fp16
__device__ __half g_wp[(size_t)NEMBD * NEMBD];            // w_proj^T fp16
__device__ __half g_q_hi[(size_t)BH * TSEQ * HDIM];       // [bh][t][d], pre-scaled
__device__ __half g_q_lo[(size_t)BH * TSEQ * HDIM];
__device__ __half g_k[(size_t)BH * TSEQ * HDIM];
__device__ __half g_v[(size_t)BH * TSEQ * HDIM];

// ---------------------------------------------------------------------------
// PTX helpers
// ---------------------------------------------------------------------------
__device__ __forceinline__ uint32_t smem_u32(const void* p) {
    uint32_t a;
    asm("{ .reg .u64 t; cvta.to.shared.u64 t, %1; cvt.u32.u64 %0, t; }" : "=r"(a) : "l"(p));
    return a;
}
#define CP_ASYNC16(sm, gm) \
    asm volatile("cp.async.cg.shared.global [%0], [%1], 16;" :: "r"(sm), "l"(gm))
#define CP_COMMIT() asm volatile("cp.async.commit_group;" ::: "memory")
#define CP_WAIT(n)  asm volatile("cp.async.wait_group %0;" :: "n"(n) : "memory")

#define LDSM_X4(r0, r1, r2, r3, a) \
    asm volatile("ldmatrix.sync.aligned.m8n8.x4.shared.b16 {%0,%1,%2,%3}, [%4];" \
        : "=r"(r0), "=r"(r1), "=r"(r2), "=r"(r3) : "r"(a))
#define LDSM_X4_T(r0, r1, r2, r3, a) \
    asm volatile("ldmatrix.sync.aligned.m8n8.x4.trans.shared.b16 {%0,%1,%2,%3}, [%4];" \
        : "=r"(r0), "=r"(r1), "=r"(r2), "=r"(r3) : "r"(a))

__device__ __forceinline__ void mma_bb(float* c, const uint32_t* a, uint32_t b0, uint32_t b1) {
    asm volatile(
        "mma.sync.aligned.m16n8k16.row.col.f32.f16.f16.f32 "
        "{%0,%1,%2,%3}, {%4,%5,%6,%7}, {%8,%9}, {%0,%1,%2,%3};"
        : "+f"(c[0]), "+f"(c[1]), "+f"(c[2]), "+f"(c[3])
        : "r"(a[0]), "r"(a[1]), "r"(a[2]), "r"(a[3]), "r"(b0), "r"(b1));
}
__device__ __forceinline__ uint32_t pack_h2(float a, float b) {
    __half2 h = __floats2half2_rn(a, b);
    return *(uint32_t*)&h;
}
__device__ __forceinline__ float exp2p(float t) {
    t = fmaxf(t, -126.0f);
    float fi = rintf(t);
    float f = t - fi;
    float p = 0.0013333558f;
    p = fmaf(p, f, 0.0096181291f);
    p = fmaf(p, f, 0.0555041087f);
    p = fmaf(p, f, 0.2402265070f);
    p = fmaf(p, f, 0.6931471806f);
    p = fmaf(p, f, 1.0f);
    int ii = (int)fi;
    return p * __int_as_float((uint32_t)(ii + 127) << 23);
}

// ---------------------------------------------------------------------------
// Conversion kernels
// ---------------------------------------------------------------------------
__global__ __launch_bounds__(256)
void convert_kernel(const float* __restrict__ in, __half* __restrict__ out, int n4)
{
    int idx = blockIdx.x * blockDim.x + threadIdx.x;
    if (idx >= n4) return;
    float4 v = ((const float4*)in)[idx];
    __half h[4] = {__float2half_rn(v.x), __float2half_rn(v.y),
                   __float2half_rn(v.z), __float2half_rn(v.w)};
    ((uint2*)out)[idx] = *(const uint2*)h;
}

__global__ __launch_bounds__(256)
void tsplit_kernel(const float* __restrict__ w, __half* __restrict__ wt, int K, int N)
{
    __shared__ float t[32][33];
    const int n0 = blockIdx.x * 32;
    const int k0 = blockIdx.y * 32;
#pragma unroll
    for (int i = 0; i < 4; ++i) {
        int kk = threadIdx.y + i * 8;
        t[kk][threadIdx.x] = w[(size_t)(k0 + kk) * N + n0 + threadIdx.x];
    }
    __syncthreads();
#pragma unroll
    for (int i = 0; i < 4; ++i) {
        int nn = threadIdx.y + i * 8;
        int kk = threadIdx.x;
        wt[(size_t)(n0 + nn) * K + k0 + kk] = __float2half_rn(t[kk][nn]);
    }
}

// ---------------------------------------------------------------------------
// Shared tile constants
// ---------------------------------------------------------------------------
#define BK 32
#define ASTR 40
#define A_TILE_B (128 * ASTR * 2)
#define B128_TILE_B (128 * ASTR * 2)

// ---------------------------------------------------------------------------
// 1-product GEMM, BN=128. MODE 0: fp32 C.  MODE 1: qkv epilogue
// (sec 0: q scaled hi/lo; sec 1: k fp16; sec 2: v fp16).
// ---------------------------------------------------------------------------
#define GBUFW (A_TILE_B + B128_TILE_B)
#define SMEMW (3 * GBUFW)

template<int MODE>
__global__ __launch_bounds__(256, 2)
void gemm_wide_kernel(const __half* __restrict__ Ah,
                      const __half* __restrict__ B,
                      float* __restrict__ C,
                      uint32_t* __restrict__ qhi, uint32_t* __restrict__ qlo,
                      uint32_t* __restrict__ kk, uint32_t* __restrict__ vv,
                      int N, int K)
{
    extern __shared__ char smem[];
    const uint32_t sbase = smem_u32(smem);
    const int tid = threadIdx.x;
    const int wid = tid >> 5;
    const int lane = tid & 31;
    const int grp = lane >> 2;
    const int tig = lane & 3;
    const int warp_m = wid & 3;
    const int warp_n = wid >> 2;
    const int rowBase = blockIdx.y * 128;
    const int colBase = blockIdx.x * 128;

    const int a_row = lane & 15;
    const int a_kh  = (lane >> 4) * 8;
    uint32_t aoff[2];
#pragma unroll
    for (int mt = 0; mt < 2; ++mt)
        aoff[mt] = (uint32_t)(((warp_m * 32 + mt * 16 + a_row) * ASTR + a_kh) * 2);
    const int b_n  = (lane & 7) + ((lane >> 4) & 1) * 8;
    const int b_kh = ((lane >> 3) & 1) * 8;
    uint32_t boff[4];
#pragma unroll
    for (int np = 0; np < 4; ++np)
        boff[np] = (uint32_t)(((warp_n * 64 + np * 16 + b_n) * ASTR + b_kh) * 2);

    float acc[2][8][4];
#pragma unroll
    for (int i = 0; i < 2; ++i)
#pragma unroll
        for (int j = 0; j < 8; ++j)
#pragma unroll
            for (int k = 0; k < 4; ++k) acc[i][j][k] = 0.0f;

    const int nstages = K / BK;

#define LOAD_STAGE_W(s) do {                                                    \
        const int _k0 = (s) * BK;                                               \
        const uint32_t _buf = sbase + ((s) % 3) * GBUFW;                        \
        _Pragma("unroll")                                                       \
        for (int _i = 0; _i < 2; ++_i) {                                        \
            int _idx = tid + _i * 256;                                          \
            int _r = _idx >> 2, _c = _idx & 3;                                  \
            CP_ASYNC16(_buf + _r * (ASTR * 2) + _c * 16,                        \
                       Ah + (size_t)(rowBase + _r) * K + _k0 + _c * 8);         \
            CP_ASYNC16(_buf + A_TILE_B + _r * (ASTR * 2) + _c * 16,             \
                       B + (size_t)(colBase + _r) * K + _k0 + _c * 8);          \
        }                                                                       \
        CP_COMMIT();                                                            \
    } while (0)

    LOAD_STAGE_W(0);
    LOAD_STAGE_W(1);

    for (int s = 0; s < nstages; ++s) {
        if (s + 2 < nstages) { LOAD_STAGE_W(s + 2); CP_WAIT(2); }
        else if (s + 1 < nstages) { CP_WAIT(1); }
        else { CP_WAIT(0); }
        __syncthreads();

        const uint32_t buf = sbase + (s % 3) * GBUFW;
        const uint32_t smA = buf;
        const uint32_t smB = buf + A_TILE_B;

#pragma unroll
        for (int kkk = 0; kkk < BK; kkk += 16) {
            uint32_t ah[2][4], bf[4][4];
#pragma unroll
            for (int mt = 0; mt < 2; ++mt)
                LDSM_X4(ah[mt][0], ah[mt][1], ah[mt][2], ah[mt][3], smA + aoff[mt] + kkk * 2);
#pragma unroll
            for (int np = 0; np < 4; ++np)
                LDSM_X4(bf[np][0], bf[np][1], bf[np][2], bf[np][3], smB + boff[np] + kkk * 2);
#pragma unroll
            for (int mt = 0; mt < 2; ++mt)
#pragma unroll
                for (int nt = 0; nt < 8; ++nt)
                    mma_bb(acc[mt][nt], ah[mt],
                           bf[nt >> 1][(nt & 1) * 2], bf[nt >> 1][(nt & 1) * 2 + 1]);
        }
        __syncthreads();
    }

    if (MODE == 0) {
#pragma unroll
        for (int mt = 0; mt < 2; ++mt) {
            int r = rowBase + warp_m * 32 + mt * 16 + grp;
#pragma unroll
            for (int nt = 0; nt < 8; ++nt) {
                int c = colBase + warp_n * 64 + nt * 8 + tig * 2;
                *(float2*)(C + (size_t)r * N + c) = make_float2(acc[mt][nt][0], acc[mt][nt][1]);
                *(float2*)(C + (size_t)(r + 8) * N + c) = make_float2(acc[mt][nt][2], acc[mt][nt][3]);
            }
        }
    } else {
        // qkv epilogue: col in [0,3072), 64 cols per head.
#pragma unroll
        for (int mt = 0; mt < 2; ++mt) {
            const int r0 = rowBase + warp_m * 32 + mt * 16 + grp;
#pragma unroll
            for (int hf = 0; hf < 2; ++hf) {
                const int r = r0 + hf * 8;
                const int b = r >> 11;
                const int t = r & (TSEQ - 1);
#pragma unroll
                for (int nt = 0; nt < 8; ++nt) {
                    const int col = colBase + warp_n * 64 + nt * 8;
                    const int sec = col >> 10;           // 0=q, 1=k, 2=v
                    const int h = (col & 1023) >> 6;
                    const int dw = ((col & 63) >> 1) + tig;
                    const size_t bhT = (size_t)(b * NHEAD + h) * TSEQ + t;
                    float v0 = acc[mt][nt][hf * 2], v1 = acc[mt][nt][hf * 2 + 1];
                    if (sec == 0) {
                        float q0 = v0 * QSCALE, q1 = v1 * QSCALE;
                        uint32_t hp = pack_h2(q0, q1);
                        float2 fr = __half22float2(*(__half2*)&hp);
                        qhi[bhT * 32 + dw] = hp;
                        qlo[bhT * 32 + dw] = pack_h2(q0 - fr.x, q1 - fr.y);
                    } else {
                        uint32_t hp = pack_h2(v0, v1);
                        if (sec == 1) kk[bhT * 32 + dw] = hp;
                        else          vv[bhT * 32 + dw] = hp;
                    }
                }
            }
        }
    }
#undef LOAD_STAGE_W
}

// ---------------------------------------------------------------------------
// HMMA flash attention: S 2-product (Q hi/lo), P@V 1-product via ldmatrix.trans.
// ---------------------------------------------------------------------------
#define AQ  128
#define AKV 64
#define KSW 36
#define VSW 36
#define QHI_W 0
#define QLO_W 4608
#define STG0_W 9216
#define STG_SZ_W 4608
#define KOFF_W 0
#define VOFF_W 2304
#define ATTN_SMEM_B ((STG0_W + 2 * STG_SZ_W) * 4)

__global__ __launch_bounds__(256, 2)
void attn_hmma_kernel(const __half* __restrict__ Qh, const __half* __restrict__ Ql,
                      const __half* __restrict__ Kt, const __half* __restrict__ Vh,
                      uint32_t* __restrict__ yhi)
{
    extern __shared__ uint32_t smw[];
    const uint32_t sbase = smem_u32(smw);
    const int tid = threadIdx.x;
    const int warp = tid >> 5;
    const int lane = tid & 31;
    const int grp = lane >> 2;
    const int tig = lane & 3;
    const int qb = (int)(gridDim.x - 1 - blockIdx.x);
    const int bh = blockIdx.y;
    const int q0 = qb * AQ;
    const size_t bhT = (size_t)bh * TSEQ;

    const int a_row = lane & 15;
    const int a_kh  = (lane >> 4) * 8;
    const int b_n   = (lane & 7) + ((lane >> 4) & 1) * 8;
    const int b_kh  = ((lane >> 3) & 1) * 8;

#pragma unroll
    for (int i = 0; i < 4; ++i) {
        int idx = tid + i * 256;
        int r = idx >> 3, c = idx & 7;
        CP_ASYNC16(sbase + (QHI_W + r * KSW) * 4 + c * 16, Qh + (bhT + q0 + r) * HDIM + c * 8);
        CP_ASYNC16(sbase + (QLO_W + r * KSW) * 4 + c * 16, Ql + (bhT + q0 + r) * HDIM + c * 8);
    }
    CP_COMMIT();

#define LOAD_KV(kb_, st_) do {                                                          \
        const int _kv0 = (kb_) * AKV;                                                  \
        const uint32_t _sb = sbase + (STG0_W + (st_) * STG_SZ_W) * 4;                   \
        _Pragma("unroll")                                                               \
        for (int _i = 0; _i < 2; ++_i) {                                                \
            int _idx = tid + _i * 256;                                                  \
            int _r = _idx >> 3, _c = _idx & 7;                                          \
            CP_ASYNC16(_sb + (KOFF_W + _r * KSW) * 4 + _c * 16,                         \
                       Kt + (bhT + _kv0 + _r) * HDIM + _c * 8);                         \
        }                                                                               \
        _Pragma("unroll")                                                               \
        for (int _i = 0; _i < 2; ++_i) {                                                \
            int _idx = tid + _i * 256;                                                  \
            int _r = _idx >> 3, _c = _idx & 7;                                          \
            CP_ASYNC16(_sb + (VOFF_W + _r * VSW) * 4 + _c * 16,                         \
                       Vh + (bhT + _kv0 + _r) * HDIM + _c * 8);                         \
        }                                                                               \
        CP_COMMIT();                                                                    \
    } while (0)

    LOAD_KV(0, 0);
    CP_WAIT(0);
    __syncthreads();

    uint32_t qfh[4][4], qfl[4][4];
    {
        const uint32_t qrow = (uint32_t)((warp * 16 + a_row) * KSW);
#pragma unroll
        for (int ks = 0; ks < 4; ++ks) {
            uint32_t ao = sbase + (QHI_W + qrow) * 4 + (ks * 16 + a_kh) * 2;
            LDSM_X4(qfh[ks][0], qfh[ks][1], qfh[ks][2], qfh[ks][3], ao);
            uint32_t al_ = ao + (QLO_W - QHI_W) * 4;
            LDSM_X4(qfl[ks][0], qfl[ks][1], qfl[ks][2], qfl[ks][3], al_);
        }
    }

    float o[8][4];
#pragma unroll
    for (int i = 0; i < 8; ++i)
#pragma unroll
        for (int j = 0; j < 4; ++j) o[i][j] = 0.0f;
    float m0 = -1e30f, m1 = -1e30f, l0 = 0.0f, l1 = 0.0f;

    const int nkb = 2 * (qb + 1);
    for (int kb = 0; kb < nkb; ++kb) {
        if (kb) { CP_WAIT(0); __syncthreads(); }
        if (kb + 1 < nkb) LOAD_KV(kb + 1, (kb + 1) & 1);

        const uint32_t stw = STG0_W + (kb & 1) * STG_SZ_W;
        const uint32_t kW = stw + KOFF_W;
        const uint32_t vW = stw + VOFF_W;

        float s[8][4];
#pragma unroll
        for (int i = 0; i < 8; ++i)
            s[i][0] = s[i][1] = s[i][2] = s[i][3] = 0.0f;
#pragma unroll
        for (int np = 0; np < 4; ++np) {
            const uint32_t krow = sbase + (kW + (np * 16 + b_n) * KSW) * 4;
#pragma unroll
            for (int ks = 0; ks < 4; ++ks) {
                uint32_t b0, b1, b2, b3;
                LDSM_X4(b0, b1, b2, b3, krow + (ks * 16 + b_kh) * 2);
                mma_bb(s[np * 2],     qfh[ks], b0, b1);
                mma_bb(s[np * 2],     qfl[ks], b0, b1);
                mma_bb(s[np * 2 + 1], qfh[ks], b2, b3);
                mma_bb(s[np * 2 + 1], qfl[ks], b2, b3);
            }
        }

        if (kb >= nkb - 2) {
            const int kv0 = kb * AKV;
            const int r0g = q0 + warp * 16 + grp;
            const int r1g = r0g + 8;
#pragma unroll
            for (int nt = 0; nt < 8; ++nt) {
                int c0 = kv0 + nt * 8 + tig * 2;
                if (c0 > r0g)     s[nt][0] = -1e30f;
                if (c0 + 1 > r0g) s[nt][1] = -1e30f;
                if (c0 > r1g)     s[nt][2] = -1e30f;
                if (c0 + 1 > r1g) s[nt][3] = -1e30f;
            }
        }

        float mx0 = -1e30f, mx1 = -1e30f;
#pragma unroll
        for (int nt = 0; nt < 8; ++nt) {
            mx0 = fmaxf(mx0, fmaxf(s[nt][0], s[nt][1]));
            mx1 = fmaxf(mx1, fmaxf(s[nt][2], s[nt][3]));
        }
        mx0 = fmaxf(mx0, __shfl_xor_sync(0xffffffffu, mx0, 1));
        mx0 = fmaxf(mx0, __shfl_xor_sync(0xffffffffu, mx0, 2));
        mx1 = fmaxf(mx1, __shfl_xor_sync(0xffffffffu, mx1, 1));
        mx1 = fmaxf(mx1, __shfl_xor_sync(0xffffffffu, mx1, 2));
        float mn0 = fmaxf(m0, mx0), mn1 = fmaxf(m1, mx1);
        float a0 = exp2p(m0 - mn0), a1 = exp2p(m1 - mn1);
        m0 = mn0; m1 = mn1;
        l0 *= a0; l1 *= a1;
#pragma unroll
        for (int nt = 0; nt < 8; ++nt) {
            o[nt][0] *= a0; o[nt][1] *= a0;
            o[nt][2] *= a1; o[nt][3] *= a1;
        }
        float sum0 = 0.0f, sum1 = 0.0f;
#pragma unroll
        for (int nt = 0; nt < 8; ++nt) {
            float p0 = exp2p(s[nt][0] - m0);
            float p1 = exp2p(s[nt][1] - m0);
            float p2 = exp2p(s[nt][2] - m1);
            float p3 = exp2p(s[nt][3] - m1);
            sum0 += p0 + p1; sum1 += p2 + p3;
            s[nt][0] = p0; s[nt][1] = p1; s[nt][2] = p2; s[nt][3] = p3;
        }
        l0 += sum0; l1 += sum1;

#pragma unroll
        for (int j = 0; j < 4; ++j) {
            uint32_t ah4[4];
#pragma unroll
            for (int u = 0; u < 2; ++u) {
                const float* pv = s[2 * j + u];
                ah4[u * 2 + 0] = pack_h2(pv[0], pv[1]);
                ah4[u * 2 + 1] = pack_h2(pv[2], pv[3]);
            }
#pragma unroll
            for (int np = 0; np < 4; ++np) {
                uint32_t v0, v1, v2, v3;
                uint32_t vaddr = sbase + (vW + (j * 16 + a_row) * VSW) * 4
                               + (np * 16 + a_kh) * 2;
                LDSM_X4_T(v0, v1, v2, v3, vaddr);
                mma_bb(o[np * 2],     ah4, v0, v1);
                mma_bb(o[np * 2 + 1], ah4, v2, v3);
            }
        }
    }

    l0 += __shfl_xor_sync(0xffffffffu, l0, 1);
    l0 += __shfl_xor_sync(0xffffffffu, l0, 2);
    l1 += __shfl_xor_sync(0xffffffffu, l1, 1);
    l1 += __shfl_xor_sync(0xffffffffu, l1, 2);
    const float inv0 = 1.0f / l0, inv1 = 1.0f / l1;

    const int b = bh >> 4, h = bh & 15;
    const int rowg = q0 + warp * 16 + grp;
    const size_t base0 = ((size_t)(b * TSEQ) + rowg) * (NEMBD / 2) + h * (HDIM / 2);
    const size_t base1 = base0 + 8 * (NEMBD / 2);
#pragma unroll
    for (int nt = 0; nt < 8; ++nt) {
        int cw = nt * 4 + tig;
        yhi[base0 + cw] = pack_h2(o[nt][0] * inv0, o[nt][1] * inv0);
        yhi[base1 + cw] = pack_h2(o[nt][2] * inv1, o[nt][3] * inv1);
    }
#undef LOAD_KV
}

// ---------------------------------------------------------------------------
// Launch
// ---------------------------------------------------------------------------
extern "C" void kernel_launch(void* const* d_in, const int* in_sizes, int n_in,
                              void* d_out, int out_size)
{
    const float* x      = (const float*)d_in[0];
    const float* w_attn = (const float*)d_in[1];
    const float* w_proj = (const float*)d_in[2];
    float* out = (float*)d_out;

    __half *aa, *wq, *wp, *qhi, *qlo, *kk, *vv;
    cudaGetSymbolAddress((void**)&aa, g_a);
    cudaGetSymbolAddress((void**)&wq, g_wq);
    cudaGetSymbolAddress((void**)&wp, g_wp);
    cudaGetSymbolAddress((void**)&qhi, g_q_hi);
    cudaGetSymbolAddress((void**)&qlo, g_q_lo);
    cudaGetSymbolAddress((void**)&kk, g_k);
    cudaGetSymbolAddress((void**)&vv, g_v);

    cudaFuncSetAttribute(gemm_wide_kernel<0>,
                         cudaFuncAttributeMaxDynamicSharedMemorySize, SMEMW);
    cudaFuncSetAttribute(gemm_wide_kernel<1>,
                         cudaFuncAttributeMaxDynamicSharedMemorySize, SMEMW);
    cudaFuncSetAttribute(attn_hmma_kernel,
                         cudaFuncAttributeMaxDynamicSharedMemorySize, ATTN_SMEM_B);

    const int M = BATCH * TSEQ;   // 8192
    const int K = NEMBD;          // 1024

    // Convert x -> fp16
    {
        int n4 = (M * K) / 4;
        convert_kernel<<<(n4 + 255) / 256, 256>>>(x, aa, n4);
    }
    // Transpose weights -> fp16
    {
        dim3 g1((3 * NEMBD) / 32, K / 32);
        tsplit_kernel<<<g1, dim3(32, 8)>>>(w_attn, wq, K, 3 * NEMBD);
        dim3 g2(NEMBD / 32, K / 32);
        tsplit_kernel<<<g2, dim3(32, 8)>>>(w_proj, wp, K, NEMBD);
    }
    // Stage 1: full qkv GEMM (1-product, BN=128) -> q hi/lo scaled, k, v fp16
    {
        dim3 grid((3 * NEMBD) / 128, M / 128);
        gemm_wide_kernel<1><<<grid, 256, SMEMW>>>(
            aa, wq, nullptr,
            (uint32_t*)qhi, (uint32_t*)qlo, (uint32_t*)kk, (uint32_t*)vv, 0, K);
    }
    // Stage 2: flash attention -> y fp16 (into g_a)
    {
        dim3 grid(TSEQ / AQ, BH);
        attn_hmma_kernel<<<grid, 256, ATTN_SMEM_B>>>(qhi, qlo, kk, vv, (uint32_t*)aa);
    }
    // Stage 3: out = y @ w_proj (1-product, BN=128)
    {
        dim3 grid(NEMBD / 128, M / 128);
        gemm_wide_kernel<0><<<grid, 256, SMEMW>>>(
            aa, wp, out, nullptr, nullptr, nullptr, nullptr, NEMBD, K);
    }
}